// round 4
// baseline (speedup 1.0000x reference)
#include <cuda_runtime.h>
#include <cstdint>

// MeanAggregator: out[i] = sum_{j in edges[i]} nodes[edges[i][j]] / n_nodes
// Reference shapes: N = 40000 nodes, DEG = 16, D = 128 (fp32).
// NOTE: the reference asks for int64 edges, but JAX without x64 enabled
// silently produces int32 — the harness buffer is int32. Index accordingly.
// Layout: one warp per node; lane l owns float4 chunk l (32 * 4 = 128 floats).

#define D_FEAT 128
#define D_VEC (D_FEAT / 4)   // 32 float4 per row = 1 per lane
#define DEG_FAST 16

__global__ __launch_bounds__(256) void mean_agg_kernel(
    const float4* __restrict__ nodes,   // [n_nodes * 32] float4
    const int* __restrict__ edges,      // [n_nodes * deg] int32
    float4* __restrict__ out,           // [n_nodes * 32] float4
    int n_nodes, int deg, float inv_n)
{
    const int warp_id = (blockIdx.x * blockDim.x + threadIdx.x) >> 5;
    const int lane = threadIdx.x & 31;
    if (warp_id >= n_nodes) return;

    const int* e = edges + (long long)warp_id * deg;
    float4 acc = make_float4(0.f, 0.f, 0.f, 0.f);

    if (deg == DEG_FAST) {
        // Load all 16 neighbor indices first (uniform across warp -> broadcast;
        // 16 x int32 = 2 cachelines per warp).
        int idx[DEG_FAST];
#pragma unroll
        for (int j = 0; j < DEG_FAST; ++j) {
            idx[j] = __ldg(&e[j]);
        }
        // 16 independent gathers for high MLP; nodes (~20 MB) is L2-resident.
#pragma unroll
        for (int j = 0; j < DEG_FAST; ++j) {
            float4 v = __ldg(&nodes[idx[j] * D_VEC + lane]);
            acc.x += v.x; acc.y += v.y; acc.z += v.z; acc.w += v.w;
        }
    } else {
        // Generic path: unroll by 4 to keep some MLP.
        int j = 0;
        for (; j + 4 <= deg; j += 4) {
            int i0 = __ldg(&e[j + 0]);
            int i1 = __ldg(&e[j + 1]);
            int i2 = __ldg(&e[j + 2]);
            int i3 = __ldg(&e[j + 3]);
            float4 v0 = __ldg(&nodes[i0 * D_VEC + lane]);
            float4 v1 = __ldg(&nodes[i1 * D_VEC + lane]);
            float4 v2 = __ldg(&nodes[i2 * D_VEC + lane]);
            float4 v3 = __ldg(&nodes[i3 * D_VEC + lane]);
            acc.x += v0.x + v1.x + v2.x + v3.x;
            acc.y += v0.y + v1.y + v2.y + v3.y;
            acc.z += v0.z + v1.z + v2.z + v3.z;
            acc.w += v0.w + v1.w + v2.w + v3.w;
        }
        for (; j < deg; ++j) {
            int i0 = __ldg(&e[j]);
            float4 v = __ldg(&nodes[i0 * D_VEC + lane]);
            acc.x += v.x; acc.y += v.y; acc.z += v.z; acc.w += v.w;
        }
    }

    out[(long long)warp_id * D_VEC + lane] =
        make_float4(acc.x * inv_n, acc.y * inv_n, acc.z * inv_n, acc.w * inv_n);
}

extern "C" void kernel_launch(void* const* d_in, const int* in_sizes, int n_in,
                              void* d_out, int out_size)
{
    const float4* nodes = (const float4*)d_in[0];
    const int* edges = (const int*)d_in[1];
    float4* out = (float4*)d_out;

    // Derive shapes: nodes is [n, 128] f32, edges is [n, deg] i32 (element counts).
    const int n_nodes = in_sizes[0] / D_FEAT;
    const int deg = in_sizes[1] / n_nodes;
    const float inv_n = 1.0f / (float)n_nodes;

    // One warp per node, 8 warps (256 threads) per block.
    const int threads = 256;
    const int warps_per_block = threads / 32;
    const int blocks = (n_nodes + warps_per_block - 1) / warps_per_block;
    mean_agg_kernel<<<blocks, threads>>>(nodes, edges, out, n_nodes, deg, inv_n);
}